// round 1
// baseline (speedup 1.0000x reference)
#include <cuda_runtime.h>
#include <stdint.h>

// Problem constants
#define DIM   1024
#define HID   2048
#define NEXP  8
#define NTOK  2048
#define NROWS 4096   // NTOK * top_k(2)

// ---------------- device scratch (static, no runtime alloc) ----------------
__device__ int   g_counts[NEXP];
__device__ int   g_cursor[NEXP];
__device__ int   g_off[NEXP + 1];
__device__ int   g_topk_idx[NROWS];
__device__ float g_topk_score[NROWS];
__device__ int   g_row_token[NROWS];
__device__ float g_X[(size_t)NROWS * DIM];       // 16 MB, routed+scaled inputs
__device__ float g_H[(size_t)NROWS * HID];       // 32 MB, SwiGLU hidden

// ---------------- helpers ----------------
__device__ __forceinline__ float f2tf(float x) {
    unsigned u;
    asm("cvt.rna.tf32.f32 %0, %1;" : "=r"(u) : "f"(x));
    return __uint_as_float(u);
}

__device__ __forceinline__ void mma_tf32(float* c, const unsigned* a, const unsigned* b) {
    asm volatile(
        "mma.sync.aligned.m16n8k8.row.col.f32.tf32.tf32.f32 "
        "{%0,%1,%2,%3},{%4,%5,%6,%7},{%8,%9},{%0,%1,%2,%3};\n"
        : "+f"(c[0]), "+f"(c[1]), "+f"(c[2]), "+f"(c[3])
        : "r"(a[0]), "r"(a[1]), "r"(a[2]), "r"(a[3]), "r"(b[0]), "r"(b[1]));
}

// ---------------- kernel 0: zero counters ----------------
__global__ void k_zero() {
    if (threadIdx.x < NEXP) g_counts[threadIdx.x] = 0;
}

// ---------------- kernel 1: router (logits -> softmax -> top2) ----------------
__global__ void k_router(const float* __restrict__ x, const float* __restrict__ rw) {
    int t = blockIdx.x;
    const float* xr = x + (size_t)t * DIM;
    float acc[NEXP];
#pragma unroll
    for (int e = 0; e < NEXP; e++) acc[e] = 0.f;
    for (int d = threadIdx.x; d < DIM; d += 128) {
        float xv = xr[d];
        const float* r = rw + (size_t)d * NEXP;
#pragma unroll
        for (int e = 0; e < NEXP; e++) acc[e] += xv * r[e];
    }
#pragma unroll
    for (int o = 16; o; o >>= 1)
#pragma unroll
        for (int e = 0; e < NEXP; e++) acc[e] += __shfl_down_sync(0xffffffffu, acc[e], o);

    __shared__ float s[4][NEXP];
    int warp = threadIdx.x >> 5, lane = threadIdx.x & 31;
    if (lane == 0)
#pragma unroll
        for (int e = 0; e < NEXP; e++) s[warp][e] = acc[e];
    __syncthreads();
    if (threadIdx.x == 0) {
        float l[NEXP];
#pragma unroll
        for (int e = 0; e < NEXP; e++) l[e] = s[0][e] + s[1][e] + s[2][e] + s[3][e];
        float m = l[0];
#pragma unroll
        for (int e = 1; e < NEXP; e++) m = fmaxf(m, l[e]);
        float p[NEXP]; float sum = 0.f;
#pragma unroll
        for (int e = 0; e < NEXP; e++) { p[e] = expf(l[e] - m); sum += p[e]; }
        int i0 = 0;
#pragma unroll
        for (int e = 1; e < NEXP; e++) if (p[e] > p[i0]) i0 = e;
        int i1 = (i0 == 0) ? 1 : 0;
#pragma unroll
        for (int e = 0; e < NEXP; e++) if (e != i0 && p[e] > p[i1]) i1 = e;
        float inv = 1.f / sum;
        g_topk_idx[2 * t]     = i0; g_topk_score[2 * t]     = p[i0] * inv;
        g_topk_idx[2 * t + 1] = i1; g_topk_score[2 * t + 1] = p[i1] * inv;
        atomicAdd(&g_counts[i0], 1);
        atomicAdd(&g_counts[i1], 1);
    }
}

// ---------------- kernel 2: exclusive scan of counts ----------------
__global__ void k_scan() {
    if (threadIdx.x == 0) {
        int s = 0;
        for (int e = 0; e < NEXP; e++) { g_off[e] = s; s += g_counts[e]; g_cursor[e] = 0; }
        g_off[NEXP] = s;
    }
}

// ---------------- kernel 3: dispatch (bucket + pre-scale copy) ----------------
__global__ void k_dispatch(const float* __restrict__ x) {
    int slot = blockIdx.x;
    int t = slot >> 1;
    __shared__ int sp;
    if (threadIdx.x == 0) {
        int e = g_topk_idx[slot];
        int p = g_off[e] + atomicAdd(&g_cursor[e], 1);
        g_row_token[p] = t;
        sp = p;
    }
    __syncthreads();
    int p = sp;
    float sc = g_topk_score[slot];
    const float4* src = (const float4*)(x + (size_t)t * DIM);
    float4* dst = (float4*)(g_X + (size_t)p * DIM);
    for (int i = threadIdx.x; i < DIM / 4; i += 128) {
        float4 v = src[i];
        v.x *= sc; v.y *= sc; v.z *= sc; v.w *= sc;
        dst[i] = v;
    }
}

// ---------------- GEMM tiling ----------------
#define BM 128
#define BN 64
#define BK 16
#define SA 20   // As row stride (floats): conflict-free for frag reads
#define SB 72   // Bs row stride (floats): 8 mod 32 -> conflict-free, 16B aligned

// kernel 4: fused GEMM1 (X@w1, X@w3) + SwiGLU -> g_H
__global__ __launch_bounds__(256) void k_gemm1(const float* __restrict__ w1,
                                               const float* __restrict__ w3) {
    int e = blockIdx.z;
    int base = g_off[e];
    int ne = g_off[e + 1] - base;
    int m0 = blockIdx.y * BM;
    if (m0 >= ne) return;
    int n0 = blockIdx.x * BN;
    const float* B1 = w1 + (size_t)e * DIM * HID;
    const float* B3 = w3 + (size_t)e * DIM * HID;
    const float* A  = g_X + (size_t)base * DIM;

    __shared__ float As[BM][SA];
    __shared__ float Bs1[BK][SB];
    __shared__ float Bs3[BK][SB];

    int tid = threadIdx.x;
    int warp = tid >> 5, lane = tid & 31;
    int gid = lane >> 2, tig = lane & 3;
    int wm = (warp >> 1) * 32, wn = (warp & 1) * 32;

    float acc1[2][4][4], acc3[2][4][4];
#pragma unroll
    for (int mi = 0; mi < 2; mi++)
#pragma unroll
        for (int ni = 0; ni < 4; ni++)
#pragma unroll
            for (int q = 0; q < 4; q++) { acc1[mi][ni][q] = 0.f; acc3[mi][ni][q] = 0.f; }

    for (int k0 = 0; k0 < DIM; k0 += BK) {
        // A tile: 128x16
#pragma unroll
        for (int i = 0; i < 2; i++) {
            int f4 = tid + i * 256;
            int r = f4 >> 2, c4 = (f4 & 3) * 4;
            float4 v = make_float4(0.f, 0.f, 0.f, 0.f);
            if (m0 + r < ne) v = *(const float4*)(A + (size_t)(m0 + r) * DIM + k0 + c4);
            As[r][c4]     = f2tf(v.x);
            As[r][c4 + 1] = f2tf(v.y);
            As[r][c4 + 2] = f2tf(v.z);
            As[r][c4 + 3] = f2tf(v.w);
        }
        // B tiles: 16x64 each
        {
            int r = tid >> 4, c4 = (tid & 15) * 4;
            float4 v = *(const float4*)(B1 + (size_t)(k0 + r) * HID + n0 + c4);
            *(float4*)&Bs1[r][c4] = make_float4(f2tf(v.x), f2tf(v.y), f2tf(v.z), f2tf(v.w));
            float4 u = *(const float4*)(B3 + (size_t)(k0 + r) * HID + n0 + c4);
            *(float4*)&Bs3[r][c4] = make_float4(f2tf(u.x), f2tf(u.y), f2tf(u.z), f2tf(u.w));
        }
        __syncthreads();
#pragma unroll
        for (int ks = 0; ks < BK; ks += 8) {
            unsigned af[2][4];
#pragma unroll
            for (int mi = 0; mi < 2; mi++) {
                int r = wm + mi * 16 + gid;
                af[mi][0] = __float_as_uint(As[r][ks + tig]);
                af[mi][1] = __float_as_uint(As[r + 8][ks + tig]);
                af[mi][2] = __float_as_uint(As[r][ks + tig + 4]);
                af[mi][3] = __float_as_uint(As[r + 8][ks + tig + 4]);
            }
            unsigned bf1[4][2], bf3[4][2];
#pragma unroll
            for (int ni = 0; ni < 4; ni++) {
                int n = wn + ni * 8 + gid;
                bf1[ni][0] = __float_as_uint(Bs1[ks + tig][n]);
                bf1[ni][1] = __float_as_uint(Bs1[ks + tig + 4][n]);
                bf3[ni][0] = __float_as_uint(Bs3[ks + tig][n]);
                bf3[ni][1] = __float_as_uint(Bs3[ks + tig + 4][n]);
            }
#pragma unroll
            for (int mi = 0; mi < 2; mi++)
#pragma unroll
                for (int ni = 0; ni < 4; ni++) {
                    mma_tf32(acc1[mi][ni], af[mi], bf1[ni]);
                    mma_tf32(acc3[mi][ni], af[mi], bf3[ni]);
                }
        }
        __syncthreads();
    }
    // epilogue: SwiGLU -> g_H
#pragma unroll
    for (int mi = 0; mi < 2; mi++)
#pragma unroll
        for (int ni = 0; ni < 4; ni++)
#pragma unroll
            for (int q = 0; q < 4; q++) {
                int r = wm + mi * 16 + gid + ((q >= 2) ? 8 : 0);
                int c = wn + ni * 8 + 2 * tig + (q & 1);
                int row = m0 + r;
                if (row < ne) {
                    float g = acc1[mi][ni][q];
                    float u = acc3[mi][ni][q];
                    float h = g / (1.f + __expf(-g)) * u;
                    g_H[(size_t)(base + row) * HID + n0 + c] = h;
                }
            }
}

// kernel 5: GEMM2 (H@w2) + scatter-add combine into out
__global__ __launch_bounds__(256) void k_gemm2(const float* __restrict__ w2,
                                               float* __restrict__ out) {
    int e = blockIdx.z;
    int base = g_off[e];
    int ne = g_off[e + 1] - base;
    int m0 = blockIdx.y * BM;
    if (m0 >= ne) return;
    int n0 = blockIdx.x * BN;
    const float* B = w2 + (size_t)e * HID * DIM;
    const float* A = g_H + (size_t)base * HID;

    __shared__ float As[BM][SA];
    __shared__ float Bs[BK][SB];

    int tid = threadIdx.x;
    int warp = tid >> 5, lane = tid & 31;
    int gid = lane >> 2, tig = lane & 3;
    int wm = (warp >> 1) * 32, wn = (warp & 1) * 32;

    float acc[2][4][4];
#pragma unroll
    for (int mi = 0; mi < 2; mi++)
#pragma unroll
        for (int ni = 0; ni < 4; ni++)
#pragma unroll
            for (int q = 0; q < 4; q++) acc[mi][ni][q] = 0.f;

    for (int k0 = 0; k0 < HID; k0 += BK) {
#pragma unroll
        for (int i = 0; i < 2; i++) {
            int f4 = tid + i * 256;
            int r = f4 >> 2, c4 = (f4 & 3) * 4;
            float4 v = make_float4(0.f, 0.f, 0.f, 0.f);
            if (m0 + r < ne) v = *(const float4*)(A + (size_t)(m0 + r) * HID + k0 + c4);
            As[r][c4]     = f2tf(v.x);
            As[r][c4 + 1] = f2tf(v.y);
            As[r][c4 + 2] = f2tf(v.z);
            As[r][c4 + 3] = f2tf(v.w);
        }
        {
            int r = tid >> 4, c4 = (tid & 15) * 4;
            float4 v = *(const float4*)(B + (size_t)(k0 + r) * DIM + n0 + c4);
            *(float4*)&Bs[r][c4] = make_float4(f2tf(v.x), f2tf(v.y), f2tf(v.z), f2tf(v.w));
        }
        __syncthreads();
#pragma unroll
        for (int ks = 0; ks < BK; ks += 8) {
            unsigned af[2][4];
#pragma unroll
            for (int mi = 0; mi < 2; mi++) {
                int r = wm + mi * 16 + gid;
                af[mi][0] = __float_as_uint(As[r][ks + tig]);
                af[mi][1] = __float_as_uint(As[r + 8][ks + tig]);
                af[mi][2] = __float_as_uint(As[r][ks + tig + 4]);
                af[mi][3] = __float_as_uint(As[r + 8][ks + tig + 4]);
            }
            unsigned bf[4][2];
#pragma unroll
            for (int ni = 0; ni < 4; ni++) {
                int n = wn + ni * 8 + gid;
                bf[ni][0] = __float_as_uint(Bs[ks + tig][n]);
                bf[ni][1] = __float_as_uint(Bs[ks + tig + 4][n]);
            }
#pragma unroll
            for (int mi = 0; mi < 2; mi++)
#pragma unroll
                for (int ni = 0; ni < 4; ni++)
                    mma_tf32(acc[mi][ni], af[mi], bf[ni]);
        }
        __syncthreads();
    }
    // epilogue: scatter-add to output rows
#pragma unroll
    for (int mi = 0; mi < 2; mi++)
#pragma unroll
        for (int ni = 0; ni < 4; ni++)
#pragma unroll
            for (int q = 0; q < 4; q++) {
                int r = wm + mi * 16 + gid + ((q >= 2) ? 8 : 0);
                int c = wn + ni * 8 + 2 * tig + (q & 1);
                int row = m0 + r;
                if (row < ne) {
                    int tok = g_row_token[base + row];
                    atomicAdd(&out[(size_t)tok * DIM + n0 + c], acc[mi][ni][q]);
                }
            }
}

// ---------------- launch ----------------
extern "C" void kernel_launch(void* const* d_in, const int* in_sizes, int n_in,
                              void* d_out, int out_size) {
    const float* x  = (const float*)d_in[0];
    const float* rw = (const float*)d_in[1];
    const float* w1 = (const float*)d_in[2];
    const float* w2 = (const float*)d_in[3];
    const float* w3 = (const float*)d_in[4];
    float* out = (float*)d_out;

    cudaMemsetAsync(out, 0, (size_t)NTOK * DIM * sizeof(float));
    k_zero<<<1, 32>>>();
    k_router<<<NTOK, 128>>>(x, rw);
    k_scan<<<1, 32>>>();
    k_dispatch<<<NROWS, 128>>>(x);
    k_gemm1<<<dim3(HID / BN, NROWS / BM, NEXP), 256>>>(w1, w3);
    k_gemm2<<<dim3(DIM / BN, NROWS / BM, NEXP), 256>>>(w2, out);
}

// round 2
// speedup vs baseline: 1.4609x; 1.4609x over previous
#include <cuda_runtime.h>
#include <stdint.h>

// Problem constants
#define DIM   1024
#define HID   2048
#define NEXP  8
#define NTOK  2048
#define NROWS 4096   // NTOK * top_k(2)

// ---------------- device scratch (static, no runtime alloc) ----------------
__device__ int   g_counts[NEXP];
__device__ int   g_cursor[NEXP];
__device__ int   g_off[NEXP + 1];
__device__ int   g_topk_idx[NROWS];
__device__ float g_topk_score[NROWS];
__device__ int   g_row_token[NROWS];
__device__ float g_X[(size_t)NROWS * DIM];       // 16 MB, routed+scaled inputs (tf32-rounded)
__device__ float g_H[(size_t)NROWS * HID];       // 32 MB, SwiGLU hidden (tf32-rounded)

// ---------------- helpers ----------------
__device__ __forceinline__ float f2tf(float x) {
    unsigned u;
    asm("cvt.rna.tf32.f32 %0, %1;" : "=r"(u) : "f"(x));
    return __uint_as_float(u);
}

__device__ __forceinline__ void mma_tf32(float* c, const unsigned* a, const unsigned* b) {
    asm volatile(
        "mma.sync.aligned.m16n8k8.row.col.f32.tf32.tf32.f32 "
        "{%0,%1,%2,%3},{%4,%5,%6,%7},{%8,%9},{%0,%1,%2,%3};\n"
        : "+f"(c[0]), "+f"(c[1]), "+f"(c[2]), "+f"(c[3])
        : "r"(a[0]), "r"(a[1]), "r"(a[2]), "r"(a[3]), "r"(b[0]), "r"(b[1]));
}

__device__ __forceinline__ void cp_async16(void* smem_dst, const void* gsrc, int src_bytes) {
    unsigned s = (unsigned)__cvta_generic_to_shared(smem_dst);
    asm volatile("cp.async.cg.shared.global [%0], [%1], 16, %2;\n"
                 :: "r"(s), "l"(gsrc), "r"(src_bytes));
}
__device__ __forceinline__ void cp_commit() {
    asm volatile("cp.async.commit_group;\n" ::: "memory");
}
template <int N>
__device__ __forceinline__ void cp_wait() {
    asm volatile("cp.async.wait_group %0;\n" :: "n"(N) : "memory");
}

// ---------------- kernel 0: init (zero output + counters) ----------------
__global__ void k_init(float* __restrict__ out) {
    size_t i = (size_t)blockIdx.x * blockDim.x + threadIdx.x;   // 2048*256 threads, 1 float4 each
    ((float4*)out)[i] = make_float4(0.f, 0.f, 0.f, 0.f);
    if (blockIdx.x == 0 && threadIdx.x < NEXP) g_counts[threadIdx.x] = 0;
}

// ---------------- kernel 1: router (logits -> softmax -> top2) ----------------
__global__ void k_router(const float* __restrict__ x, const float* __restrict__ rw) {
    int t = blockIdx.x;
    const float* xr = x + (size_t)t * DIM;
    float acc[NEXP];
#pragma unroll
    for (int e = 0; e < NEXP; e++) acc[e] = 0.f;
    for (int d = threadIdx.x; d < DIM; d += 128) {
        float xv = xr[d];
        const float* r = rw + (size_t)d * NEXP;
#pragma unroll
        for (int e = 0; e < NEXP; e++) acc[e] += xv * r[e];
    }
#pragma unroll
    for (int o = 16; o; o >>= 1)
#pragma unroll
        for (int e = 0; e < NEXP; e++) acc[e] += __shfl_down_sync(0xffffffffu, acc[e], o);

    __shared__ float s[4][NEXP];
    int warp = threadIdx.x >> 5, lane = threadIdx.x & 31;
    if (lane == 0)
#pragma unroll
        for (int e = 0; e < NEXP; e++) s[warp][e] = acc[e];
    __syncthreads();
    if (threadIdx.x == 0) {
        float l[NEXP];
#pragma unroll
        for (int e = 0; e < NEXP; e++) l[e] = s[0][e] + s[1][e] + s[2][e] + s[3][e];
        float m = l[0];
#pragma unroll
        for (int e = 1; e < NEXP; e++) m = fmaxf(m, l[e]);
        float p[NEXP]; float sum = 0.f;
#pragma unroll
        for (int e = 0; e < NEXP; e++) { p[e] = expf(l[e] - m); sum += p[e]; }
        int i0 = 0;
#pragma unroll
        for (int e = 1; e < NEXP; e++) if (p[e] > p[i0]) i0 = e;
        int i1 = (i0 == 0) ? 1 : 0;
#pragma unroll
        for (int e = 0; e < NEXP; e++) if (e != i0 && p[e] > p[i1]) i1 = e;
        float inv = 1.f / sum;
        g_topk_idx[2 * t]     = i0; g_topk_score[2 * t]     = p[i0] * inv;
        g_topk_idx[2 * t + 1] = i1; g_topk_score[2 * t + 1] = p[i1] * inv;
        atomicAdd(&g_counts[i0], 1);
        atomicAdd(&g_counts[i1], 1);
    }
}

// ---------------- kernel 2: exclusive scan of counts ----------------
__global__ void k_scan() {
    if (threadIdx.x == 0) {
        int s = 0;
        for (int e = 0; e < NEXP; e++) { g_off[e] = s; s += g_counts[e]; g_cursor[e] = 0; }
        g_off[NEXP] = s;
    }
}

// ---------------- kernel 3: dispatch (bucket + pre-scale + tf32-round copy) --
__global__ void k_dispatch(const float* __restrict__ x) {
    int slot = blockIdx.x;
    int t = slot >> 1;
    __shared__ int sp;
    if (threadIdx.x == 0) {
        int e = g_topk_idx[slot];
        int p = g_off[e] + atomicAdd(&g_cursor[e], 1);
        g_row_token[p] = t;
        sp = p;
    }
    __syncthreads();
    int p = sp;
    float sc = g_topk_score[slot];
    const float4* src = (const float4*)(x + (size_t)t * DIM);
    float4* dst = (float4*)(g_X + (size_t)p * DIM);
    for (int i = threadIdx.x; i < DIM / 4; i += 128) {
        float4 v = src[i];
        v.x = f2tf(v.x * sc); v.y = f2tf(v.y * sc);
        v.z = f2tf(v.z * sc); v.w = f2tf(v.w * sc);
        dst[i] = v;
    }
}

// ---------------- GEMM tiling ----------------
#define BM 128
#define BN 64
#define BK 32
#define SA 36   // As row stride (floats): 16B-aligned, conflict-free frag reads
#define SB 72   // Bs row stride (floats): 16B-aligned, conflict-free frag reads
#define STAGES 3

#define A_FLOATS   (BM * SA)          // 4608
#define B_FLOATS   (BK * SB)          // 2304
#define ST1_FLOATS (A_FLOATS + 2 * B_FLOATS)   // gemm1 stage: A + B1 + B3
#define ST2_FLOATS (A_FLOATS + B_FLOATS)       // gemm2 stage: A + B
#define SMEM1_BYTES (STAGES * ST1_FLOATS * 4)  // 110592
#define SMEM2_BYTES (STAGES * ST2_FLOATS * 4)  // 82944

// kernel 4: fused GEMM1 (X@w1, X@w3) + SwiGLU -> g_H
__global__ __launch_bounds__(256) void k_gemm1(const float* __restrict__ w1,
                                               const float* __restrict__ w3) {
    int e = blockIdx.z;
    int base = g_off[e];
    int ne = g_off[e + 1] - base;
    int m0 = blockIdx.y * BM;
    if (m0 >= ne) return;
    int n0 = blockIdx.x * BN;
    const float* B1g = w1 + (size_t)e * DIM * HID;
    const float* B3g = w3 + (size_t)e * DIM * HID;
    const float* Ag  = g_X + (size_t)base * DIM;

    extern __shared__ float smem[];

    int tid = threadIdx.x;
    int warp = tid >> 5, lane = tid & 31;
    int gid = lane >> 2, tig = lane & 3;
    int wm = (warp >> 1) * 32, wn = (warp & 1) * 32;

    float acc1[2][4][4], acc3[2][4][4];
#pragma unroll
    for (int mi = 0; mi < 2; mi++)
#pragma unroll
        for (int ni = 0; ni < 4; ni++)
#pragma unroll
            for (int q = 0; q < 4; q++) { acc1[mi][ni][q] = 0.f; acc3[mi][ni][q] = 0.f; }

    const int NT = DIM / BK;   // 32

    // tile loader: issues cp.asyncs for tile `it` into stage `st`
    auto load_tile = [&](int it, int st) {
        float* As = smem + st * ST1_FLOATS;
        float* Bs1 = As + A_FLOATS;
        float* Bs3 = Bs1 + B_FLOATS;
        int k0 = it * BK;
        // A: 128x32 = 1024 float4, 4 per thread
#pragma unroll
        for (int j = 0; j < 4; j++) {
            int idx = tid + j * 256;
            int r = idx >> 3, c4 = (idx & 7) * 4;
            bool valid = (m0 + r) < ne;
            const float* src = Ag + (size_t)(valid ? (m0 + r) : 0) * DIM + k0 + c4;
            cp_async16(&As[r * SA + c4], src, valid ? 16 : 0);
        }
        // B1,B3: 32x64 = 512 float4 each, 2 per thread each
#pragma unroll
        for (int j = 0; j < 2; j++) {
            int idx = tid + j * 256;
            int r = idx >> 4, c4 = (idx & 15) * 4;
            cp_async16(&Bs1[r * SB + c4], B1g + (size_t)(k0 + r) * HID + n0 + c4, 16);
            cp_async16(&Bs3[r * SB + c4], B3g + (size_t)(k0 + r) * HID + n0 + c4, 16);
        }
    };

#pragma unroll
    for (int p = 0; p < STAGES; p++) {
        if (p < NT) load_tile(p, p);
        cp_commit();
    }

    for (int it = 0; it < NT; ++it) {
        cp_wait<STAGES - 1>();
        __syncthreads();
        int st = it % STAGES;
        float* As = smem + st * ST1_FLOATS;
        float* Bs1 = As + A_FLOATS;
        float* Bs3 = Bs1 + B_FLOATS;

        // in-place tf32 rounding of B tiles (A is pre-rounded)
#pragma unroll
        for (int j = 0; j < 2; j++) {
            int idx = tid + j * 256;
            int r = idx >> 4, c4 = (idx & 15) * 4;
            float4* p1 = (float4*)&Bs1[r * SB + c4];
            float4 v = *p1;
            *p1 = make_float4(f2tf(v.x), f2tf(v.y), f2tf(v.z), f2tf(v.w));
            float4* p3 = (float4*)&Bs3[r * SB + c4];
            float4 u = *p3;
            *p3 = make_float4(f2tf(u.x), f2tf(u.y), f2tf(u.z), f2tf(u.w));
        }
        __syncthreads();

#pragma unroll
        for (int ks = 0; ks < BK; ks += 8) {
            unsigned af[2][4];
#pragma unroll
            for (int mi = 0; mi < 2; mi++) {
                int r = wm + mi * 16 + gid;
                af[mi][0] = __float_as_uint(As[r * SA + ks + tig]);
                af[mi][1] = __float_as_uint(As[(r + 8) * SA + ks + tig]);
                af[mi][2] = __float_as_uint(As[r * SA + ks + tig + 4]);
                af[mi][3] = __float_as_uint(As[(r + 8) * SA + ks + tig + 4]);
            }
            unsigned bf1[4][2], bf3[4][2];
#pragma unroll
            for (int ni = 0; ni < 4; ni++) {
                int n = wn + ni * 8 + gid;
                bf1[ni][0] = __float_as_uint(Bs1[(ks + tig) * SB + n]);
                bf1[ni][1] = __float_as_uint(Bs1[(ks + tig + 4) * SB + n]);
                bf3[ni][0] = __float_as_uint(Bs3[(ks + tig) * SB + n]);
                bf3[ni][1] = __float_as_uint(Bs3[(ks + tig + 4) * SB + n]);
            }
#pragma unroll
            for (int mi = 0; mi < 2; mi++)
#pragma unroll
                for (int ni = 0; ni < 4; ni++) {
                    mma_tf32(acc1[mi][ni], af[mi], bf1[ni]);
                    mma_tf32(acc3[mi][ni], af[mi], bf3[ni]);
                }
        }
        __syncthreads();
        if (it + STAGES < NT) load_tile(it + STAGES, st);
        cp_commit();
    }

    // epilogue: SwiGLU -> g_H (tf32-rounded, float2 stores)
#pragma unroll
    for (int mi = 0; mi < 2; mi++)
#pragma unroll
        for (int ni = 0; ni < 4; ni++)
#pragma unroll
            for (int half = 0; half < 2; half++) {
                int r = wm + mi * 16 + gid + half * 8;
                int row = m0 + r;
                if (row < ne) {
                    float g0 = acc1[mi][ni][half * 2 + 0];
                    float g1 = acc1[mi][ni][half * 2 + 1];
                    float u0 = acc3[mi][ni][half * 2 + 0];
                    float u1 = acc3[mi][ni][half * 2 + 1];
                    float h0 = f2tf(g0 / (1.f + __expf(-g0)) * u0);
                    float h1 = f2tf(g1 / (1.f + __expf(-g1)) * u1);
                    int c = wn + ni * 8 + 2 * tig;
                    *(float2*)&g_H[(size_t)(base + row) * HID + n0 + c] = make_float2(h0, h1);
                }
            }
}

// kernel 5: GEMM2 (H@w2) + scatter-add combine into out
__global__ __launch_bounds__(256) void k_gemm2(const float* __restrict__ w2,
                                               float* __restrict__ out) {
    int e = blockIdx.z;
    int base = g_off[e];
    int ne = g_off[e + 1] - base;
    int m0 = blockIdx.y * BM;
    if (m0 >= ne) return;
    int n0 = blockIdx.x * BN;
    const float* Bg = w2 + (size_t)e * HID * DIM;
    const float* Ag = g_H + (size_t)base * HID;

    extern __shared__ float smem[];

    int tid = threadIdx.x;
    int warp = tid >> 5, lane = tid & 31;
    int gid = lane >> 2, tig = lane & 3;
    int wm = (warp >> 1) * 32, wn = (warp & 1) * 32;

    float acc[2][4][4];
#pragma unroll
    for (int mi = 0; mi < 2; mi++)
#pragma unroll
        for (int ni = 0; ni < 4; ni++)
#pragma unroll
            for (int q = 0; q < 4; q++) acc[mi][ni][q] = 0.f;

    const int NT = HID / BK;   // 64

    auto load_tile = [&](int it, int st) {
        float* As = smem + st * ST2_FLOATS;
        float* Bs = As + A_FLOATS;
        int k0 = it * BK;
#pragma unroll
        for (int j = 0; j < 4; j++) {
            int idx = tid + j * 256;
            int r = idx >> 3, c4 = (idx & 7) * 4;
            bool valid = (m0 + r) < ne;
            const float* src = Ag + (size_t)(valid ? (m0 + r) : 0) * HID + k0 + c4;
            cp_async16(&As[r * SA + c4], src, valid ? 16 : 0);
        }
#pragma unroll
        for (int j = 0; j < 2; j++) {
            int idx = tid + j * 256;
            int r = idx >> 4, c4 = (idx & 15) * 4;
            cp_async16(&Bs[r * SB + c4], Bg + (size_t)(k0 + r) * DIM + n0 + c4, 16);
        }
    };

#pragma unroll
    for (int p = 0; p < STAGES; p++) {
        if (p < NT) load_tile(p, p);
        cp_commit();
    }

    for (int it = 0; it < NT; ++it) {
        cp_wait<STAGES - 1>();
        __syncthreads();
        int st = it % STAGES;
        float* As = smem + st * ST2_FLOATS;
        float* Bs = As + A_FLOATS;

#pragma unroll
        for (int j = 0; j < 2; j++) {
            int idx = tid + j * 256;
            int r = idx >> 4, c4 = (idx & 15) * 4;
            float4* pb = (float4*)&Bs[r * SB + c4];
            float4 v = *pb;
            *pb = make_float4(f2tf(v.x), f2tf(v.y), f2tf(v.z), f2tf(v.w));
        }
        __syncthreads();

#pragma unroll
        for (int ks = 0; ks < BK; ks += 8) {
            unsigned af[2][4];
#pragma unroll
            for (int mi = 0; mi < 2; mi++) {
                int r = wm + mi * 16 + gid;
                af[mi][0] = __float_as_uint(As[r * SA + ks + tig]);
                af[mi][1] = __float_as_uint(As[(r + 8) * SA + ks + tig]);
                af[mi][2] = __float_as_uint(As[r * SA + ks + tig + 4]);
                af[mi][3] = __float_as_uint(As[(r + 8) * SA + ks + tig + 4]);
            }
            unsigned bf[4][2];
#pragma unroll
            for (int ni = 0; ni < 4; ni++) {
                int n = wn + ni * 8 + gid;
                bf[ni][0] = __float_as_uint(Bs[(ks + tig) * SB + n]);
                bf[ni][1] = __float_as_uint(Bs[(ks + tig + 4) * SB + n]);
            }
#pragma unroll
            for (int mi = 0; mi < 2; mi++)
#pragma unroll
                for (int ni = 0; ni < 4; ni++)
                    mma_tf32(acc[mi][ni], af[mi], bf[ni]);
        }
        __syncthreads();
        if (it + STAGES < NT) load_tile(it + STAGES, st);
        cp_commit();
    }

    // epilogue: scatter-add to output rows
#pragma unroll
    for (int mi = 0; mi < 2; mi++)
#pragma unroll
        for (int ni = 0; ni < 4; ni++)
#pragma unroll
            for (int q = 0; q < 4; q++) {
                int r = wm + mi * 16 + gid + ((q >= 2) ? 8 : 0);
                int c = wn + ni * 8 + 2 * tig + (q & 1);
                int row = m0 + r;
                if (row < ne) {
                    int tok = g_row_token[base + row];
                    atomicAdd(&out[(size_t)tok * DIM + n0 + c], acc[mi][ni][q]);
                }
            }
}

// ---------------- launch ----------------
extern "C" void kernel_launch(void* const* d_in, const int* in_sizes, int n_in,
                              void* d_out, int out_size) {
    const float* x  = (const float*)d_in[0];
    const float* rw = (const float*)d_in[1];
    const float* w1 = (const float*)d_in[2];
    const float* w2 = (const float*)d_in[3];
    const float* w3 = (const float*)d_in[4];
    float* out = (float*)d_out;

    static int configured = 0;
    if (!configured) {
        cudaFuncSetAttribute(k_gemm1, cudaFuncAttributeMaxDynamicSharedMemorySize, SMEM1_BYTES);
        cudaFuncSetAttribute(k_gemm2, cudaFuncAttributeMaxDynamicSharedMemorySize, SMEM2_BYTES);
        configured = 1;
    }

    k_init<<<NTOK, 256>>>(out);                   // zero out + counters
    k_router<<<NTOK, 128>>>(x, rw);
    k_scan<<<1, 32>>>();
    k_dispatch<<<NROWS, 128>>>(x);
    k_gemm1<<<dim3(HID / BN, NROWS / BM, NEXP), 256, SMEM1_BYTES>>>(w1, w3);
    k_gemm2<<<dim3(DIM / BN, NROWS / BM, NEXP), 256, SMEM2_BYTES>>>(w2, out);
}